// round 1
// baseline (speedup 1.0000x reference)
#include <cuda_runtime.h>
#include <math.h>

#define Bn 1024
#define Tn 128
#define Dn 64
#define Hn 256
#define K2 384   // 2D + H = 128 + 256

// ---------------- device state / packed weights (no allocs allowed) ----------------
__device__ float g_hA[Bn * Hn];      // h state (output of LSTM step)
__device__ float g_hB[Bn * Hn];      // decayed h (input to LSTM step)
__device__ float g_cS[Bn * Hn];      // c state (updated in place)
__device__ float g_Wc[K2 * 1024];    // [384][1024] combined [lstm_k; lstm_rk]
__device__ float g_tdhWt[Dn * Hn];   // td_h_W transposed -> [k][h]
__device__ float g_tdxWt[Dn * Dn];   // td_x_W transposed -> [k][j]
__device__ float g_frWt[Dn * Dn];    // fr_W transposed  -> [k][j]

// ---------------- init kernels ----------------
__global__ void k_zero() {
    int i = blockIdx.x * blockDim.x + threadIdx.x; // Bn*Hn = 262144
    g_hA[i] = 0.f;
    g_cS[i] = 0.f;
}

__global__ void k_pack(const float* __restrict__ lk, const float* __restrict__ lrk) {
    int i = blockIdx.x * blockDim.x + threadIdx.x; // 384*1024
    int k = i >> 10, c = i & 1023;
    g_Wc[i] = (k < 128) ? lk[k * 1024 + c] : lrk[(k - 128) * 1024 + c];
}

__global__ void k_trans(const float* __restrict__ tdh, const float* __restrict__ tdx,
                        const float* __restrict__ fr) {
    int i = blockIdx.x * blockDim.x + threadIdx.x; // 24576 total
    if (i < Dn * Hn) {
        int j = i & 255, k = i >> 8;               // out [k][j]
        g_tdhWt[i] = tdh[j * Dn + k];
    } else if (i < Dn * Hn + Dn * Dn) {
        int o = i - Dn * Hn;
        int j = o & 63, k = o >> 6;
        g_tdxWt[o] = tdx[j * Dn + k];
    } else {
        int o = i - Dn * Hn - Dn * Dn;
        int j = o & 63, k = o >> 6;
        g_frWt[o] = fr[j * Dn + k];
    }
}

// ---------------- per-step fused pre-LSTM kernel ----------------
// gamma_h, h *= gamma_h (hA -> hB), x_h, gamma_x, x_c, z_h, alpha, c_h, c_c
__global__ void __launch_bounds__(256) step_pre(
    const float* __restrict__ values, const float* __restrict__ masks,
    const float* __restrict__ deltas,
    const float* __restrict__ tdh_b, const float* __restrict__ tdx_b,
    const float* __restrict__ histW, const float* __restrict__ hist_b,
    const float* __restrict__ fr_b,
    const float* __restrict__ wcW, const float* __restrict__ wc_b,
    float* __restrict__ imp, int t)
{
    __shared__ float d_s[Dn], m_s[Dn], x_s[Dn], h_s[Hn];
    __shared__ float xh_s[Dn], gx_s[Dn], xc_s[Dn];
    __shared__ float red[4][Dn];

    int tid = threadIdx.x;
    int j = tid & 63, q = tid >> 6;

    for (int r = 0; r < 8; ++r) {
        int row = blockIdx.x * 8 + r;
        long base = ((long)row * Tn + t) * Dn;

        if (tid < Dn) {
            d_s[tid] = deltas[base + tid];
            m_s[tid] = masks[base + tid];
            x_s[tid] = values[base + tid];
        }
        __syncthreads();

        // gamma_h (all 256 threads, one H-column each), decay h
        {
            float acc = tdh_b[tid];
            #pragma unroll 16
            for (int k = 0; k < Dn; ++k) acc += d_s[k] * g_tdhWt[k * Hn + tid];
            float gh = expf(-fmaxf(acc, 0.f));
            float hd = g_hA[row * Hn + tid] * gh;
            g_hB[row * Hn + tid] = hd;
            h_s[tid] = hd;
        }
        __syncthreads();

        // x_h = h @ histW (256-len dot split over 4 thread groups)
        {
            float p = 0.f;
            #pragma unroll 16
            for (int k = 0; k < Dn; ++k) p += h_s[q * Dn + k] * histW[(q * Dn + k) * Dn + j];
            red[q][j] = p;
        }
        __syncthreads();

        if (tid < Dn) {
            float xh = red[0][j] + red[1][j] + red[2][j] + red[3][j] + hist_b[j];
            float ax = tdx_b[j];
            #pragma unroll 16
            for (int k = 0; k < Dn; ++k) ax += d_s[k] * g_tdxWt[k * Dn + j];
            float gx = expf(-fmaxf(ax, 0.f));
            float mm = m_s[j];
            float xc = mm * x_s[j] + (1.f - mm) * xh;
            gx_s[j] = gx; xc_s[j] = xc; xh_s[j] = xh;
        }
        __syncthreads();

        if (tid < Dn) {
            float zh = fr_b[j];
            #pragma unroll 16
            for (int k = 0; k < Dn; ++k) zh += xc_s[k] * g_frWt[k * Dn + j];
            float al = wc_b[j];
            #pragma unroll 16
            for (int k = 0; k < Dn; ++k) al += gx_s[k] * wcW[k * Dn + j];
            #pragma unroll 16
            for (int k = 0; k < Dn; ++k) al += m_s[k] * wcW[(Dn + k) * Dn + j];
            float ch = al * zh + (1.f - al) * xh_s[j];
            float mm = m_s[j];
            imp[base + j] = mm * x_s[j] + (1.f - mm) * ch;  // c_c (imputation output)
        }
        __syncthreads();
    }
}

// ---------------- per-step LSTM GEMM + gates + state update ----------------
// z = [c_c, m, h_dec] @ Wc + b ; i,f,g,o ; c = f*c + i*g ; h = o*tanh(c)
// Block: 32 rows x 64 h-cols (x4 gates). Grid (32, 4).
__global__ void __launch_bounds__(256) step_lstm(
    const float* __restrict__ masks, const float* __restrict__ lstm_b,
    const float* __restrict__ imp, int t)
{
    __shared__ float xs[32 * 33];       // [row][k] padded
    __shared__ float ws[32 * 256];      // [k][gate*64 + n]

    int tid = threadIdx.x;
    int tx = tid & 15;                  // 4 cols each
    int ty = tid >> 4;                  // 2 rows each
    int rb = blockIdx.x * 32;
    int cb = blockIdx.y * 64;

    float acc[2][4][4];
    #pragma unroll
    for (int r = 0; r < 2; ++r)
        #pragma unroll
        for (int g = 0; g < 4; ++g)
            #pragma unroll
            for (int n = 0; n < 4; ++n) acc[r][g][n] = 0.f;

    int wg = tid >> 6, wn = tid & 63;   // for ws loads

    for (int kt = 0; kt < 12; ++kt) {
        int k0 = kt * 32;

        // load x-tile: 32 rows x 32 k, assembled from [c_c | m | h_dec]
        #pragma unroll
        for (int i = 0; i < 4; ++i) {
            int idx = tid + i * 256;
            int row = idx >> 5, kk = idx & 31;
            int kg = k0 + kk;
            int rowg = rb + row;
            float v;
            if (kg < 64)        v = imp[((long)rowg * Tn + t) * Dn + kg];
            else if (kg < 128)  v = masks[((long)rowg * Tn + t) * Dn + (kg - 64)];
            else                v = g_hB[rowg * Hn + (kg - 128)];
            xs[row * 33 + kk] = v;
        }
        // load W-tile: 32 k x (4 gates x 64 cols)
        #pragma unroll
        for (int i = 0; i < 32; ++i) {
            ws[i * 256 + tid] = g_Wc[(k0 + i) * 1024 + wg * 256 + cb + wn];
        }
        __syncthreads();

        #pragma unroll
        for (int kk = 0; kk < 32; ++kk) {
            float xv0 = xs[(2 * ty) * 33 + kk];
            float xv1 = xs[(2 * ty + 1) * 33 + kk];
            #pragma unroll
            for (int g = 0; g < 4; ++g) {
                float4 w = *(const float4*)&ws[kk * 256 + g * 64 + tx * 4];
                acc[0][g][0] += xv0 * w.x; acc[0][g][1] += xv0 * w.y;
                acc[0][g][2] += xv0 * w.z; acc[0][g][3] += xv0 * w.w;
                acc[1][g][0] += xv1 * w.x; acc[1][g][1] += xv1 * w.y;
                acc[1][g][2] += xv1 * w.z; acc[1][g][3] += xv1 * w.w;
            }
        }
        __syncthreads();
    }

    // gates + state update (elementwise per (row, hcol) -> no cross-block races)
    #pragma unroll
    for (int r = 0; r < 2; ++r) {
        int rowg = rb + 2 * ty + r;
        #pragma unroll
        for (int n = 0; n < 4; ++n) {
            int hcol = cb + tx * 4 + n;
            float zi = acc[r][0][n] + lstm_b[hcol];
            float zf = acc[r][1][n] + lstm_b[256 + hcol];
            float zg = acc[r][2][n] + lstm_b[512 + hcol];
            float zo = acc[r][3][n] + lstm_b[768 + hcol];
            float ig = 1.f / (1.f + expf(-zi));
            float fg = 1.f / (1.f + expf(-zf));
            float gg = tanhf(zg);
            float og = 1.f / (1.f + expf(-zo));
            int idx = rowg * Hn + hcol;
            float cn = fg * g_cS[idx] + ig * gg;
            g_cS[idx] = cn;
            g_hA[idx] = og * tanhf(cn);
        }
    }
}

// ---------------- final projection y = h @ out_W + out_b ----------------
__global__ void k_final(const float* __restrict__ outW, const float* __restrict__ outb,
                        float* __restrict__ y)
{
    int tid = threadIdx.x;
    int w = tid >> 5, lane = tid & 31;
    int row = blockIdx.x * 8 + w;
    float p = 0.f;
    #pragma unroll
    for (int k = lane; k < Hn; k += 32) p += g_hA[row * Hn + k] * outW[k];
    #pragma unroll
    for (int off = 16; off; off >>= 1) p += __shfl_down_sync(0xffffffff, p, off);
    if (lane == 0) y[row] = p + outb[0];
}

// ---------------- launch ----------------
extern "C" void kernel_launch(void* const* d_in, const int* in_sizes, int n_in,
                              void* d_out, int out_size) {
    const float* values = (const float*)d_in[0];
    const float* masks  = (const float*)d_in[1];
    const float* deltas = (const float*)d_in[2];
    const float* td_h_W = (const float*)d_in[3];
    const float* td_h_b = (const float*)d_in[4];
    const float* td_x_W = (const float*)d_in[5];
    const float* td_x_b = (const float*)d_in[6];
    const float* hist_W = (const float*)d_in[7];
    const float* hist_b = (const float*)d_in[8];
    const float* fr_W   = (const float*)d_in[9];
    const float* fr_b   = (const float*)d_in[10];
    const float* wc_W   = (const float*)d_in[11];
    const float* wc_b   = (const float*)d_in[12];
    const float* lstm_k = (const float*)d_in[13];
    const float* lstm_rk= (const float*)d_in[14];
    const float* lstm_b = (const float*)d_in[15];
    const float* out_W  = (const float*)d_in[16];
    const float* out_b  = (const float*)d_in[17];

    float* out = (float*)d_out;
    float* y   = out;            // [B, 1]
    float* imp = out + Bn;       // [B, T, D]

    k_zero<<<(Bn * Hn) / 256, 256>>>();
    k_pack<<<(K2 * 1024) / 256, 256>>>(lstm_k, lstm_rk);
    k_trans<<<96, 256>>>(td_h_W, td_x_W, fr_W);

    for (int t = 0; t < Tn; ++t) {
        step_pre<<<Bn / 8, 256>>>(values, masks, deltas,
                                  td_h_b, td_x_b, hist_W, hist_b,
                                  fr_b, wc_W, wc_b, imp, t);
        step_lstm<<<dim3(Bn / 32, Hn / 64), 256>>>(masks, lstm_b, imp, t);
    }

    k_final<<<Bn / 8, 256>>>(out_W, out_b, y);
}

// round 5
// speedup vs baseline: 2.1115x; 2.1115x over previous
#include <cuda_runtime.h>
#include <math.h>

#define Bn 1024
#define Tn 128
#define Dn 64
#define Hn 256
#define K2 384   // 2D + H = 128 + 256

// ---------------- device state / packed weights (no allocs allowed) ----------------
__device__ float g_hA[Bn * Hn];      // h state (output of LSTM step)
__device__ float g_hB[Bn * Hn];      // decayed h (input to LSTM step)
__device__ float g_cS[Bn * Hn];      // c state (updated in place)
__device__ float g_Wc[K2 * 1024];    // [384][1024] combined [lstm_k; lstm_rk]
__device__ float g_tdhWt[Dn * Hn];   // td_h_W transposed -> [k][h]
__device__ float g_tdxWt[Dn * Dn];   // td_x_W transposed -> [k][j]
__device__ float g_frWt[Dn * Dn];    // fr_W transposed  -> [k][j]

// ---------------- f32x2 helpers ----------------
__device__ __forceinline__ void ffma2(unsigned long long &d, unsigned long long a,
                                      unsigned long long b) {
    asm("fma.rn.f32x2 %0, %1, %2, %3;" : "=l"(d) : "l"(a), "l"(b), "l"(d));
}
__device__ __forceinline__ unsigned long long pk2(float v) {
    unsigned long long r;
    unsigned int u = __float_as_uint(v);
    asm("mov.b64 %0, {%1, %2};" : "=l"(r) : "r"(u), "r"(u));
    return r;
}
__device__ __forceinline__ void upk2(float &lo, float &hi, unsigned long long v) {
    unsigned int l, h;
    asm("mov.b64 {%0, %1}, %2;" : "=r"(l), "=r"(h) : "l"(v));
    lo = __uint_as_float(l);
    hi = __uint_as_float(h);
}

// ---------------- init kernels ----------------
__global__ void k_zero() {
    int i = blockIdx.x * blockDim.x + threadIdx.x; // Bn*Hn
    g_hA[i] = 0.f;
    g_cS[i] = 0.f;
}

__global__ void k_pack(const float* __restrict__ lk, const float* __restrict__ lrk) {
    int i = blockIdx.x * blockDim.x + threadIdx.x; // 384*1024
    int k = i >> 10, c = i & 1023;
    g_Wc[i] = (k < 128) ? lk[k * 1024 + c] : lrk[(k - 128) * 1024 + c];
}

__global__ void k_trans(const float* __restrict__ tdh, const float* __restrict__ tdx,
                        const float* __restrict__ fr) {
    int i = blockIdx.x * blockDim.x + threadIdx.x; // 24576 total
    if (i < Dn * Hn) {
        int j = i & 255, k = i >> 8;               // out [k][j]
        g_tdhWt[i] = tdh[j * Dn + k];
    } else if (i < Dn * Hn + Dn * Dn) {
        int o = i - Dn * Hn;
        int j = o & 63, k = o >> 6;
        g_tdxWt[o] = tdx[j * Dn + k];
    } else {
        int o = i - Dn * Hn - Dn * Dn;
        int j = o & 63, k = o >> 6;
        g_frWt[o] = fr[j * Dn + k];
    }
}

// ---------------- per-step fused pre-LSTM kernel (8 rows in PARALLEL) ----------------
__global__ void __launch_bounds__(512) step_pre(
    const float* __restrict__ values, const float* __restrict__ masks,
    const float* __restrict__ deltas,
    const float* __restrict__ tdh_b, const float* __restrict__ tdx_b,
    const float* __restrict__ histW, const float* __restrict__ hist_b,
    const float* __restrict__ fr_b,
    const float* __restrict__ wcW, const float* __restrict__ wc_b,
    float* __restrict__ imp, int t)
{
    __shared__ float d_s[8 * 64], m_s[8 * 64], x_s[8 * 64];
    __shared__ float h_s[8 * 256];
    __shared__ float xh_s[8 * 64], gx_s[8 * 64], xc_s[8 * 64];

    int tid = threadIdx.x;
    int rb = blockIdx.x * 8;

    // load inputs: 8 rows x 64 cols, one element per thread per array
    {
        int r = tid >> 6, c = tid & 63;
        long base = ((long)(rb + r) * Tn + t) * Dn + c;
        d_s[tid] = deltas[base];
        m_s[tid] = masks[base];
        x_s[tid] = values[base];
    }
    __syncthreads();

    // ---- Stage A: gamma_h + h decay. thread = (h, row-quartet) ----
    {
        int h = tid & 255, rq = tid >> 8;   // rq in {0,1}; rows rq, rq+2, rq+4, rq+6
        float b = tdh_b[h];
        float a0 = b, a1 = b, a2 = b, a3 = b;
        #pragma unroll
        for (int k = 0; k < 64; ++k) {
            float w = g_tdhWt[k * 256 + h];
            a0 += d_s[(rq + 0) * 64 + k] * w;
            a1 += d_s[(rq + 2) * 64 + k] * w;
            a2 += d_s[(rq + 4) * 64 + k] * w;
            a3 += d_s[(rq + 6) * 64 + k] * w;
        }
        float acc[4] = {a0, a1, a2, a3};
        #pragma unroll
        for (int i = 0; i < 4; ++i) {
            int rl = rq + 2 * i;
            int row = rb + rl;
            float gh = expf(-fmaxf(acc[i], 0.f));
            float hd = g_hA[row * 256 + h] * gh;
            g_hB[row * 256 + h] = hd;
            h_s[rl * 256 + h] = hd;
        }
    }
    __syncthreads();

    // ---- Stage B: x_h = h @ histW ; gamma_x ; x_c. thread = (row, j) ----
    {
        int r = tid >> 6, j = tid & 63;
        float s0 = 0.f, s1 = 0.f, s2 = 0.f, s3 = 0.f;
        #pragma unroll
        for (int k = 0; k < 256; k += 4) {
            s0 += h_s[r * 256 + k + 0] * histW[(k + 0) * 64 + j];
            s1 += h_s[r * 256 + k + 1] * histW[(k + 1) * 64 + j];
            s2 += h_s[r * 256 + k + 2] * histW[(k + 2) * 64 + j];
            s3 += h_s[r * 256 + k + 3] * histW[(k + 3) * 64 + j];
        }
        float xh = (s0 + s1) + (s2 + s3) + hist_b[j];

        float b0 = 0.f, b1 = 0.f, b2 = 0.f, b3 = 0.f;
        #pragma unroll
        for (int k = 0; k < 64; k += 4) {
            b0 += d_s[r * 64 + k + 0] * g_tdxWt[(k + 0) * 64 + j];
            b1 += d_s[r * 64 + k + 1] * g_tdxWt[(k + 1) * 64 + j];
            b2 += d_s[r * 64 + k + 2] * g_tdxWt[(k + 2) * 64 + j];
            b3 += d_s[r * 64 + k + 3] * g_tdxWt[(k + 3) * 64 + j];
        }
        float gx = expf(-fmaxf((b0 + b1) + (b2 + b3) + tdx_b[j], 0.f));
        float mm = m_s[r * 64 + j];
        float xc = mm * x_s[r * 64 + j] + (1.f - mm) * xh;
        xh_s[r * 64 + j] = xh;
        gx_s[r * 64 + j] = gx;
        xc_s[r * 64 + j] = xc;
    }
    __syncthreads();

    // ---- Stage C: z_h, alpha, c_h, c_c. thread = (row, j) ----
    {
        int r = tid >> 6, j = tid & 63;
        float z0 = 0.f, z1 = 0.f, a0 = 0.f, a1 = 0.f;
        #pragma unroll
        for (int k = 0; k < 64; k += 2) {
            z0 += xc_s[r * 64 + k + 0] * g_frWt[(k + 0) * 64 + j];
            z1 += xc_s[r * 64 + k + 1] * g_frWt[(k + 1) * 64 + j];
            a0 += gx_s[r * 64 + k + 0] * wcW[(k + 0) * 64 + j];
            a1 += gx_s[r * 64 + k + 1] * wcW[(k + 1) * 64 + j];
        }
        #pragma unroll
        for (int k = 0; k < 64; k += 2) {
            a0 += m_s[r * 64 + k + 0] * wcW[(64 + k + 0) * 64 + j];
            a1 += m_s[r * 64 + k + 1] * wcW[(64 + k + 1) * 64 + j];
        }
        float zh = z0 + z1 + fr_b[j];
        float al = a0 + a1 + wc_b[j];
        float ch = al * zh + (1.f - al) * xh_s[r * 64 + j];
        float mm = m_s[r * 64 + j];
        imp[((long)(rb + r) * Tn + t) * Dn + j] = mm * x_s[r * 64 + j] + (1.f - mm) * ch;
    }
}

// ---------------- per-step LSTM GEMM (f32x2) + gates + state update ----------------
// Block: 32 rows x 64 h-cols (x4 gates). Grid (32, 4). 256 threads.
// Thread tile: 4 rows x 4 cols x 2 gates; z exchanged via smem (aliased over ws)
// before the fused gate epilogue.
__global__ void __launch_bounds__(256) step_lstm(
    const float* __restrict__ masks, const float* __restrict__ lstm_b,
    const float* __restrict__ imp, int t)
{
    // Single buffer, 9344 floats = 36.5KB.
    //   mainloop: xs = buf[0 .. 32*36), ws = buf[32*36 .. 32*36+32*256)
    //   epilogue: zs = buf[0 .. 32*260)  (aliases xs+ws after final sync)
    __shared__ __align__(16) float buf[32 * 36 + 32 * 256];
    float* xs = buf;
    float* ws = buf + 32 * 36;
    float* zs = buf;

    int tid = threadIdx.x;
    int tx = tid & 15;            // 4 cols each
    int ty = (tid >> 4) & 7;      // 4 rows each
    int gz = tid >> 7;            // 2 gates each (0: gates 0,1 ; 1: gates 2,3)
    int rb = blockIdx.x * 32;
    int cb = blockIdx.y * 64;

    unsigned long long acc[4][2][2];
    #pragma unroll
    for (int i = 0; i < 4; ++i)
        #pragma unroll
        for (int g = 0; g < 2; ++g) {
            acc[i][g][0] = 0ull;
            acc[i][g][1] = 0ull;
        }

    for (int kt = 0; kt < 12; ++kt) {
        int k0 = kt * 32;

        // xs: 32 rows x 32 k from [c_c | m | h_dec]
        #pragma unroll
        for (int i = 0; i < 4; ++i) {
            int idx = tid + i * 256;
            int row = idx >> 5, kk = idx & 31;
            int kg = k0 + kk;
            int rowg = rb + row;
            float v;
            if (kg < 64)       v = imp[((long)rowg * Tn + t) * Dn + kg];
            else if (kg < 128) v = masks[((long)rowg * Tn + t) * Dn + (kg - 64)];
            else               v = g_hB[rowg * Hn + (kg - 128)];
            xs[row * 36 + kk] = v;
        }
        // ws: 32 k x 256 cols, vectorized float4
        #pragma unroll
        for (int i = 0; i < 8; ++i) {
            int f = tid + i * 256;        // 2048 float4
            int row = f >> 6, c4 = f & 63;
            float4 w = *(const float4*)&g_Wc[(k0 + row) * 1024 + (c4 >> 4) * 256 + cb + ((c4 & 15) * 4)];
            *(float4*)&ws[row * 256 + c4 * 4] = w;
        }
        __syncthreads();

        #pragma unroll
        for (int kk4 = 0; kk4 < 8; ++kk4) {
            float4 xv[4];
            #pragma unroll
            for (int i = 0; i < 4; ++i)
                xv[i] = *(const float4*)&xs[(ty * 4 + i) * 36 + kk4 * 4];
            #pragma unroll
            for (int u = 0; u < 4; ++u) {
                int kk = kk4 * 4 + u;
                unsigned long long xp[4];
                #pragma unroll
                for (int i = 0; i < 4; ++i) {
                    const float* xf = (const float*)&xv[i];
                    xp[i] = pk2(xf[u]);
                }
                #pragma unroll
                for (int g2 = 0; g2 < 2; ++g2) {
                    ulonglong2 w2 = *(const ulonglong2*)&ws[kk * 256 + (gz * 2 + g2) * 64 + tx * 4];
                    #pragma unroll
                    for (int i = 0; i < 4; ++i) {
                        ffma2(acc[i][g2][0], xp[i], w2.x);
                        ffma2(acc[i][g2][1], xp[i], w2.y);
                    }
                }
            }
        }
        __syncthreads();
    }

    // write z partials to smem (aliased buffer) for gate exchange
    #pragma unroll
    for (int i = 0; i < 4; ++i) {
        int row = ty * 4 + i;
        #pragma unroll
        for (int g2 = 0; g2 < 2; ++g2) {
            float z0, z1, z2, z3;
            upk2(z0, z1, acc[i][g2][0]);
            upk2(z2, z3, acc[i][g2][1]);
            int c0 = (gz * 2 + g2) * 64 + tx * 4;
            *(float4*)&zs[row * 260 + c0] = make_float4(z0, z1, z2, z3);
        }
    }
    __syncthreads();

    // epilogue: 32x64 items, 8 per thread
    #pragma unroll
    for (int i = 0; i < 8; ++i) {
        int idx = tid + i * 256;
        int row = idx >> 6, c = idx & 63;
        int rowg = rb + row, hcol = cb + c;
        float zi = zs[row * 260 + 0 * 64 + c] + lstm_b[hcol];
        float zf = zs[row * 260 + 1 * 64 + c] + lstm_b[256 + hcol];
        float zg = zs[row * 260 + 2 * 64 + c] + lstm_b[512 + hcol];
        float zo = zs[row * 260 + 3 * 64 + c] + lstm_b[768 + hcol];
        float ig = 1.f / (1.f + expf(-zi));
        float fg = 1.f / (1.f + expf(-zf));
        float gg = tanhf(zg);
        float og = 1.f / (1.f + expf(-zo));
        int sidx = rowg * Hn + hcol;
        float cn = fg * g_cS[sidx] + ig * gg;
        g_cS[sidx] = cn;
        g_hA[sidx] = og * tanhf(cn);
    }
}

// ---------------- final projection y = h @ out_W + out_b ----------------
__global__ void k_final(const float* __restrict__ outW, const float* __restrict__ outb,
                        float* __restrict__ y)
{
    int tid = threadIdx.x;
    int w = tid >> 5, lane = tid & 31;
    int row = blockIdx.x * 8 + w;
    float p = 0.f;
    #pragma unroll
    for (int k = lane; k < Hn; k += 32) p += g_hA[row * Hn + k] * outW[k];
    #pragma unroll
    for (int off = 16; off; off >>= 1) p += __shfl_down_sync(0xffffffff, p, off);
    if (lane == 0) y[row] = p + outb[0];
}

// ---------------- launch ----------------
extern "C" void kernel_launch(void* const* d_in, const int* in_sizes, int n_in,
                              void* d_out, int out_size) {
    const float* values = (const float*)d_in[0];
    const float* masks  = (const float*)d_in[1];
    const float* deltas = (const float*)d_in[2];
    const float* td_h_W = (const float*)d_in[3];
    const float* td_h_b = (const float*)d_in[4];
    const float* td_x_W = (const float*)d_in[5];
    const float* td_x_b = (const float*)d_in[6];
    const float* hist_W = (const float*)d_in[7];
    const float* hist_b = (const float*)d_in[8];
    const float* fr_W   = (const float*)d_in[9];
    const float* fr_b   = (const float*)d_in[10];
    const float* wc_W   = (const float*)d_in[11];
    const float* wc_b   = (const float*)d_in[12];
    const float* lstm_k = (const float*)d_in[13];
    const float* lstm_rk= (const float*)d_in[14];
    const float* lstm_b = (const float*)d_in[15];
    const float* out_W  = (const float*)d_in[16];
    const float* out_b  = (const float*)d_in[17];

    float* out = (float*)d_out;
    float* y   = out;            // [B, 1]
    float* imp = out + Bn;       // [B, T, D]

    k_zero<<<(Bn * Hn) / 256, 256>>>();
    k_pack<<<(K2 * 1024) / 256, 256>>>(lstm_k, lstm_rk);
    k_trans<<<96, 256>>>(td_h_W, td_x_W, fr_W);

    for (int t = 0; t < Tn; ++t) {
        step_pre<<<Bn / 8, 512>>>(values, masks, deltas,
                                  td_h_b, td_x_b, hist_W, hist_b,
                                  fr_b, wc_W, wc_b, imp, t);
        step_lstm<<<dim3(Bn / 32, Hn / 64), 256>>>(masks, lstm_b, imp, t);
    }

    k_final<<<Bn / 8, 256>>>(out_W, out_b, y);
}

// round 6
// speedup vs baseline: 2.3655x; 1.1203x over previous
#include <cuda_runtime.h>
#include <math.h>

#define Bn 1024
#define Tn 128
#define Dn 64
#define Hn 256
#define K2 384   // 2D + H = 128 + 256

typedef unsigned long long ull;

// ---- quad-packed pre-weight layout inside g_preW / smem (float offsets) ----
#define O_TDH   0        // [16][256][4]  (k/4, h, k%4)   16384
#define O_HIST  16384    // [64][64][4]   (k/4, j, k%4)   16384
#define O_TDX   32768    // [16][64][4]                     4096
#define O_FR    36864    // [16][64][4]                     4096
#define O_WC    40960    // [32][64][4]                     8192
#define O_TDHB  49152    // 256
#define O_TDXB  49408    // 64
#define O_HISTB 49472    // 64
#define O_FRB   49536    // 64
#define O_WCB   49600    // 64
#define NW_PRE  49664
// smem-only staging buffers (after weights)
#define S_DS    49664    // 512
#define S_MS    50176    // 512
#define S_XS    50688    // 512
#define S_HS    51200    // 2048
#define S_XH    53248    // 512
#define S_GX    53760    // 512
#define S_XC    54272    // 512
#define SM_TOT  54784    // floats -> 219136 bytes

// ---------------- device state / packed weights (no allocs allowed) ----------------
__device__ float g_hA[Bn * Hn];      // h state (output of LSTM step)
__device__ float g_hB[Bn * Hn];      // decayed h (input to LSTM step)
__device__ float g_cS[Bn * Hn];      // c state (updated in place)
__device__ float g_Wc[K2 * 1024];    // [384][1024] combined [lstm_k; lstm_rk]
__device__ __align__(16) float g_preW[NW_PRE];  // quad-packed pre-LSTM weights

// ---------------- f32x2 helpers ----------------
__device__ __forceinline__ void ffma2(ull &d, ull a, ull b) {
    asm("fma.rn.f32x2 %0, %1, %2, %3;" : "=l"(d) : "l"(a), "l"(b), "l"(d));
}
__device__ __forceinline__ ull pk2(float v) {
    ull r;
    unsigned int u = __float_as_uint(v);
    asm("mov.b64 %0, {%1, %2};" : "=l"(r) : "r"(u), "r"(u));
    return r;
}
__device__ __forceinline__ void upk2(float &lo, float &hi, ull v) {
    unsigned int l, h;
    asm("mov.b64 {%0, %1}, %2;" : "=r"(l), "=r"(h) : "l"(v));
    lo = __uint_as_float(l);
    hi = __uint_as_float(h);
}
__device__ __forceinline__ float sum2(ull a) {
    float lo, hi;
    upk2(lo, hi, a);
    return lo + hi;
}

// ---------------- init kernels ----------------
__global__ void k_zero() {
    int i = blockIdx.x * blockDim.x + threadIdx.x; // Bn*Hn
    g_hA[i] = 0.f;
    g_cS[i] = 0.f;
}

__global__ void k_pack(const float* __restrict__ lk, const float* __restrict__ lrk) {
    int i = blockIdx.x * blockDim.x + threadIdx.x; // 384*1024
    int k = i >> 10, c = i & 1023;
    g_Wc[i] = (k < 128) ? lk[k * 1024 + c] : lrk[(k - 128) * 1024 + c];
}

// Build quad-packed g_preW. 194 blocks x 256 = 49664 threads, one element each.
__global__ void k_trans(const float* __restrict__ tdh, const float* __restrict__ tdx,
                        const float* __restrict__ fr, const float* __restrict__ hist,
                        const float* __restrict__ wc,
                        const float* __restrict__ tdh_b, const float* __restrict__ tdx_b,
                        const float* __restrict__ hist_b, const float* __restrict__ fr_b,
                        const float* __restrict__ wc_b) {
    int i = blockIdx.x * blockDim.x + threadIdx.x;
    if (i < 16384) {                       // td_h_W [H=256][D=64], gamma_h_h = sum_k d[k]*W[h][k]
        int k = i >> 8, h = i & 255;
        g_preW[O_TDH + ((k >> 2) * 256 + h) * 4 + (k & 3)] = tdh[h * 64 + k];
    } else if (i < 32768) {                // hist_W [256][64], x_h_j = sum_k h[k]*W[k][j]
        int o = i - 16384;
        int k = o >> 6, j = o & 63;
        g_preW[O_HIST + ((k >> 2) * 64 + j) * 4 + (k & 3)] = hist[k * 64 + j];
    } else if (i < 36864) {                // td_x_W [64][64], used d @ W.T -> W[j][k]
        int o = i - 32768;
        int k = o >> 6, j = o & 63;
        g_preW[O_TDX + ((k >> 2) * 64 + j) * 4 + (k & 3)] = tdx[j * 64 + k];
    } else if (i < 40960) {                // fr_W [64][64], x @ W.T -> W[j][k]
        int o = i - 36864;
        int k = o >> 6, j = o & 63;
        g_preW[O_FR + ((k >> 2) * 64 + j) * 4 + (k & 3)] = fr[j * 64 + k];
    } else if (i < 49152) {                // wc_W [128][64], cat @ W -> W[k][j]
        int o = i - 40960;
        int k = o >> 6, j = o & 63;
        g_preW[O_WC + ((k >> 2) * 64 + j) * 4 + (k & 3)] = wc[k * 64 + j];
    } else if (i < 49408) {
        g_preW[O_TDHB + (i - 49152)] = tdh_b[i - 49152];
    } else if (i < 49472) {
        g_preW[O_TDXB + (i - 49408)] = tdx_b[i - 49408];
    } else if (i < 49536) {
        g_preW[O_HISTB + (i - 49472)] = hist_b[i - 49472];
    } else if (i < 49600) {
        g_preW[O_FRB + (i - 49536)] = fr_b[i - 49536];
    } else if (i < NW_PRE) {
        g_preW[O_WCB + (i - 49600)] = wc_b[i - 49600];
    }
}

// ---------------- per-step fused pre-LSTM kernel: smem weights + f32x2 ----------------
// 128 blocks x 512 threads, 8 rows/block, all weights staged into dynamic smem.
__global__ void __launch_bounds__(512) step_pre(
    const float* __restrict__ values, const float* __restrict__ masks,
    const float* __restrict__ deltas, float* __restrict__ imp, int t)
{
    extern __shared__ __align__(16) float sm[];
    int tid = threadIdx.x;
    int rb = blockIdx.x * 8;

    // stage weights (coalesced float4 stream, ~1us)
    {
        const float4* gw = (const float4*)g_preW;
        float4* sw = (float4*)sm;
        #pragma unroll
        for (int i = 0; i < NW_PRE / 4 / 512 + 1; ++i) {
            int idx = tid + i * 512;
            if (idx < NW_PRE / 4) sw[idx] = gw[idx];
        }
    }
    // stage inputs: 8 rows x 64 cols
    {
        int r = tid >> 6, c = tid & 63;
        long base = ((long)(rb + r) * Tn + t) * Dn + c;
        sm[S_DS + tid] = deltas[base];
        sm[S_MS + tid] = masks[base];
        sm[S_XS + tid] = values[base];
    }
    __syncthreads();

    // ---- Stage A: gamma_h + h decay. thread = (h, row-quartet) ----
    {
        int h = tid & 255, rq = tid >> 8;   // rows rq, rq+2, rq+4, rq+6
        ull a0[4] = {0, 0, 0, 0}, a1[4] = {0, 0, 0, 0};
        #pragma unroll
        for (int k4 = 0; k4 < 16; ++k4) {
            ulonglong2 w2 = *(const ulonglong2*)&sm[O_TDH + (k4 * 256 + h) * 4];
            #pragma unroll
            for (int i = 0; i < 4; ++i) {
                int rl = rq + 2 * i;
                ulonglong2 d2 = *(const ulonglong2*)&sm[S_DS + rl * 64 + k4 * 4];
                ffma2(a0[i], d2.x, w2.x);
                ffma2(a1[i], d2.y, w2.y);
            }
        }
        float b = sm[O_TDHB + h];
        #pragma unroll
        for (int i = 0; i < 4; ++i) {
            int rl = rq + 2 * i;
            int row = rb + rl;
            float su = sum2(a0[i]) + sum2(a1[i]) + b;
            float gh = expf(-fmaxf(su, 0.f));
            float hd = g_hA[row * 256 + h] * gh;
            g_hB[row * 256 + h] = hd;
            sm[S_HS + rl * 256 + h] = hd;
        }
    }
    __syncthreads();

    // ---- Stage B: x_h = h @ histW ; gamma_x ; x_c. thread = (row, j) ----
    {
        int r = tid >> 6, j = tid & 63;
        ull za = 0, zb = 0;
        #pragma unroll
        for (int k4 = 0; k4 < 64; ++k4) {
            ulonglong2 w2 = *(const ulonglong2*)&sm[O_HIST + (k4 * 64 + j) * 4];
            ulonglong2 h2 = *(const ulonglong2*)&sm[S_HS + r * 256 + k4 * 4];
            ffma2(za, h2.x, w2.x);
            ffma2(zb, h2.y, w2.y);
        }
        float xh = sum2(za) + sum2(zb) + sm[O_HISTB + j];

        ull ga = 0, gb = 0;
        #pragma unroll
        for (int k4 = 0; k4 < 16; ++k4) {
            ulonglong2 w2 = *(const ulonglong2*)&sm[O_TDX + (k4 * 64 + j) * 4];
            ulonglong2 d2 = *(const ulonglong2*)&sm[S_DS + r * 64 + k4 * 4];
            ffma2(ga, d2.x, w2.x);
            ffma2(gb, d2.y, w2.y);
        }
        float gx = expf(-fmaxf(sum2(ga) + sum2(gb) + sm[O_TDXB + j], 0.f));
        float mm = sm[S_MS + r * 64 + j];
        float xc = mm * sm[S_XS + r * 64 + j] + (1.f - mm) * xh;
        sm[S_XH + r * 64 + j] = xh;
        sm[S_GX + r * 64 + j] = gx;
        sm[S_XC + r * 64 + j] = xc;
    }
    __syncthreads();

    // ---- Stage C: z_h, alpha, c_h, c_c. thread = (row, j) ----
    {
        int r = tid >> 6, j = tid & 63;
        ull za = 0, zb = 0, aa = 0, ab = 0;
        #pragma unroll
        for (int k4 = 0; k4 < 16; ++k4) {
            ulonglong2 w2 = *(const ulonglong2*)&sm[O_FR + (k4 * 64 + j) * 4];
            ulonglong2 x2 = *(const ulonglong2*)&sm[S_XC + r * 64 + k4 * 4];
            ffma2(za, x2.x, w2.x);
            ffma2(zb, x2.y, w2.y);
            ulonglong2 v2 = *(const ulonglong2*)&sm[O_WC + (k4 * 64 + j) * 4];
            ulonglong2 g2 = *(const ulonglong2*)&sm[S_GX + r * 64 + k4 * 4];
            ffma2(aa, g2.x, v2.x);
            ffma2(ab, g2.y, v2.y);
        }
        #pragma unroll
        for (int k4 = 16; k4 < 32; ++k4) {
            ulonglong2 v2 = *(const ulonglong2*)&sm[O_WC + (k4 * 64 + j) * 4];
            ulonglong2 m2 = *(const ulonglong2*)&sm[S_MS + r * 64 + (k4 - 16) * 4];
            ffma2(aa, m2.x, v2.x);
            ffma2(ab, m2.y, v2.y);
        }
        float zh = sum2(za) + sum2(zb) + sm[O_FRB + j];
        float al = sum2(aa) + sum2(ab) + sm[O_WCB + j];
        float ch = al * zh + (1.f - al) * sm[S_XH + r * 64 + j];
        float mm = sm[S_MS + r * 64 + j];
        imp[((long)(rb + r) * Tn + t) * Dn + j] =
            mm * sm[S_XS + r * 64 + j] + (1.f - mm) * ch;
    }
}

// ---------------- per-step LSTM GEMM (f32x2) + gates + state update ----------------
__global__ void __launch_bounds__(256) step_lstm(
    const float* __restrict__ masks, const float* __restrict__ lstm_b,
    const float* __restrict__ imp, int t)
{
    __shared__ __align__(16) float buf[32 * 36 + 32 * 256];
    float* xs = buf;
    float* ws = buf + 32 * 36;
    float* zs = buf;   // aliases xs+ws after final mainloop sync

    int tid = threadIdx.x;
    int tx = tid & 15;            // 4 cols each
    int ty = (tid >> 4) & 7;      // 4 rows each
    int gz = tid >> 7;            // 2 gates each
    int rb = blockIdx.x * 32;
    int cb = blockIdx.y * 64;

    ull acc[4][2][2];
    #pragma unroll
    for (int i = 0; i < 4; ++i)
        #pragma unroll
        for (int g = 0; g < 2; ++g) {
            acc[i][g][0] = 0ull;
            acc[i][g][1] = 0ull;
        }

    for (int kt = 0; kt < 12; ++kt) {
        int k0 = kt * 32;

        #pragma unroll
        for (int i = 0; i < 4; ++i) {
            int idx = tid + i * 256;
            int row = idx >> 5, kk = idx & 31;
            int kg = k0 + kk;
            int rowg = rb + row;
            float v;
            if (kg < 64)       v = imp[((long)rowg * Tn + t) * Dn + kg];
            else if (kg < 128) v = masks[((long)rowg * Tn + t) * Dn + (kg - 64)];
            else               v = g_hB[rowg * Hn + (kg - 128)];
            xs[row * 36 + kk] = v;
        }
        #pragma unroll
        for (int i = 0; i < 8; ++i) {
            int f = tid + i * 256;
            int row = f >> 6, c4 = f & 63;
            float4 w = *(const float4*)&g_Wc[(k0 + row) * 1024 + (c4 >> 4) * 256 + cb + ((c4 & 15) * 4)];
            *(float4*)&ws[row * 256 + c4 * 4] = w;
        }
        __syncthreads();

        #pragma unroll
        for (int kk4 = 0; kk4 < 8; ++kk4) {
            float4 xv[4];
            #pragma unroll
            for (int i = 0; i < 4; ++i)
                xv[i] = *(const float4*)&xs[(ty * 4 + i) * 36 + kk4 * 4];
            #pragma unroll
            for (int u = 0; u < 4; ++u) {
                int kk = kk4 * 4 + u;
                ull xp[4];
                #pragma unroll
                for (int i = 0; i < 4; ++i) {
                    const float* xf = (const float*)&xv[i];
                    xp[i] = pk2(xf[u]);
                }
                #pragma unroll
                for (int g2 = 0; g2 < 2; ++g2) {
                    ulonglong2 w2 = *(const ulonglong2*)&ws[kk * 256 + (gz * 2 + g2) * 64 + tx * 4];
                    #pragma unroll
                    for (int i = 0; i < 4; ++i) {
                        ffma2(acc[i][g2][0], xp[i], w2.x);
                        ffma2(acc[i][g2][1], xp[i], w2.y);
                    }
                }
            }
        }
        __syncthreads();
    }

    #pragma unroll
    for (int i = 0; i < 4; ++i) {
        int row = ty * 4 + i;
        #pragma unroll
        for (int g2 = 0; g2 < 2; ++g2) {
            float z0, z1, z2, z3;
            upk2(z0, z1, acc[i][g2][0]);
            upk2(z2, z3, acc[i][g2][1]);
            int c0 = (gz * 2 + g2) * 64 + tx * 4;
            *(float4*)&zs[row * 260 + c0] = make_float4(z0, z1, z2, z3);
        }
    }
    __syncthreads();

    #pragma unroll
    for (int i = 0; i < 8; ++i) {
        int idx = tid + i * 256;
        int row = idx >> 6, c = idx & 63;
        int rowg = rb + row, hcol = cb + c;
        float zi = zs[row * 260 + 0 * 64 + c] + lstm_b[hcol];
        float zf = zs[row * 260 + 1 * 64 + c] + lstm_b[256 + hcol];
        float zg = zs[row * 260 + 2 * 64 + c] + lstm_b[512 + hcol];
        float zo = zs[row * 260 + 3 * 64 + c] + lstm_b[768 + hcol];
        float ig = 1.f / (1.f + expf(-zi));
        float fg = 1.f / (1.f + expf(-zf));
        float gg = tanhf(zg);
        float og = 1.f / (1.f + expf(-zo));
        int sidx = rowg * Hn + hcol;
        float cn = fg * g_cS[sidx] + ig * gg;
        g_cS[sidx] = cn;
        g_hA[sidx] = og * tanhf(cn);
    }
}

// ---------------- final projection y = h @ out_W + out_b ----------------
__global__ void k_final(const float* __restrict__ outW, const float* __restrict__ outb,
                        float* __restrict__ y)
{
    int tid = threadIdx.x;
    int w = tid >> 5, lane = tid & 31;
    int row = blockIdx.x * 8 + w;
    float p = 0.f;
    #pragma unroll
    for (int k = lane; k < Hn; k += 32) p += g_hA[row * Hn + k] * outW[k];
    #pragma unroll
    for (int off = 16; off; off >>= 1) p += __shfl_down_sync(0xffffffff, p, off);
    if (lane == 0) y[row] = p + outb[0];
}

// ---------------- launch ----------------
extern "C" void kernel_launch(void* const* d_in, const int* in_sizes, int n_in,
                              void* d_out, int out_size) {
    const float* values = (const float*)d_in[0];
    const float* masks  = (const float*)d_in[1];
    const float* deltas = (const float*)d_in[2];
    const float* td_h_W = (const float*)d_in[3];
    const float* td_h_b = (const float*)d_in[4];
    const float* td_x_W = (const float*)d_in[5];
    const float* td_x_b = (const float*)d_in[6];
    const float* hist_W = (const float*)d_in[7];
    const float* hist_b = (const float*)d_in[8];
    const float* fr_W   = (const float*)d_in[9];
    const float* fr_b   = (const float*)d_in[10];
    const float* wc_W   = (const float*)d_in[11];
    const float* wc_b   = (const float*)d_in[12];
    const float* lstm_k = (const float*)d_in[13];
    const float* lstm_rk= (const float*)d_in[14];
    const float* lstm_b = (const float*)d_in[15];
    const float* out_W  = (const float*)d_in[16];
    const float* out_b  = (const float*)d_in[17];

    float* out = (float*)d_out;
    float* y   = out;            // [B, 1]
    float* imp = out + Bn;       // [B, T, D]

    static int smem_set = 0;
    if (!smem_set) {
        cudaFuncSetAttribute(step_pre, cudaFuncAttributeMaxDynamicSharedMemorySize,
                             SM_TOT * sizeof(float));
        smem_set = 1;
    }

    k_zero<<<(Bn * Hn) / 256, 256>>>();
    k_pack<<<(K2 * 1024) / 256, 256>>>(lstm_k, lstm_rk);
    k_trans<<<194, 256>>>(td_h_W, td_x_W, fr_W, hist_W, wc_W,
                          td_h_b, td_x_b, hist_b, fr_b, wc_b);

    for (int t = 0; t < Tn; ++t) {
        step_pre<<<Bn / 8, 512, SM_TOT * sizeof(float)>>>(values, masks, deltas, imp, t);
        step_lstm<<<dim3(Bn / 32, Hn / 64), 256>>>(masks, lstm_b, imp, t);
    }

    k_final<<<Bn / 8, 256>>>(out_W, out_b, y);
}